// round 16
// baseline (speedup 1.0000x reference)
#include <cuda_runtime.h>
#include <cuda_bf16.h>
#include <mma.h>
#include <cstdint>

using namespace nvcuda;

// ---- problem constants ----
#define BD   2
#define CC   256
#define NHH  8
#define NLL  5
#define NPP  16
#define HDD  32
#define MLPH 1024
#define HWW  1024
#define LQQ  5120
#define MM   10240     // B * LQ tokens
#define NPROJ 2176     // 256 + 1280 + 640

// ---- scratch (device globals; no runtime allocation allowed) ----
__device__ __align__(256) __nv_bfloat16 g_q[MM * CC];
__device__ __align__(256) __nv_bfloat16 g_hln[MM * CC];
__device__ __align__(256) __nv_bfloat16 g_samp[MM * CC];
__device__ __align__(256) __nv_bfloat16 g_mh[MM * MLPH];
__device__ __align__(256) __nv_bfloat16 g_vperm[BD * NHH * NLL * HWW * HDD];
__device__ __align__(256) float g_off[MM * 1280];
__device__ __align__(256) float g_aw[MM * 640];
__device__ __align__(256) float g_x1[MM * CC];
__device__ __align__(256) __nv_bfloat16 g_w_proj[CC * NPROJ];
__device__ __align__(256) float g_b_proj[NPROJ];
__device__ __align__(256) __nv_bfloat16 g_w_out[CC * CC];
__device__ __align__(256) __nv_bfloat16 g_w_fc1[CC * MLPH];
__device__ __align__(256) __nv_bfloat16 g_w_fc2[MLPH * CC];

// cp.async helpers
#define CP16(dst, src) \
    asm volatile("cp.async.cg.shared.global [%0], [%1], 16;" :: "r"(dst), "l"(src))
#define CP_COMMIT() asm volatile("cp.async.commit_group;" ::: "memory")
#define CP_WAIT1()  asm volatile("cp.async.wait_group 1;" ::: "memory")
#define CP_WAIT0()  asm volatile("cp.async.wait_group 0;" ::: "memory")

// =====================================================================
// LN body (shared)
// =====================================================================
__device__ __forceinline__ void ln_row(const float* __restrict__ x,
                                       const float* __restrict__ gam,
                                       const float* __restrict__ bet,
                                       __nv_bfloat16* __restrict__ out,
                                       int row, int lane) {
    const float4* xp = (const float4*)(x + (size_t)row * CC);
    float4 a = xp[lane * 2];
    float4 b = xp[lane * 2 + 1];
    float s  = a.x + a.y + a.z + a.w + b.x + b.y + b.z + b.w;
    float sq = a.x*a.x + a.y*a.y + a.z*a.z + a.w*a.w
             + b.x*b.x + b.y*b.y + b.z*b.z + b.w*b.w;
#pragma unroll
    for (int o = 16; o > 0; o >>= 1) {
        s  += __shfl_xor_sync(0xffffffffu, s,  o);
        sq += __shfl_xor_sync(0xffffffffu, sq, o);
    }
    float mean = s * (1.0f / CC);
    float var  = sq * (1.0f / CC) - mean * mean;
    float rs   = rsqrtf(var + 1e-5f);
    const float4* gp = (const float4*)gam;
    const float4* bp = (const float4*)bet;
    float4 g0 = gp[lane * 2], g1 = gp[lane * 2 + 1];
    float4 b0 = bp[lane * 2], b1 = bp[lane * 2 + 1];
    float o0 = (a.x - mean) * rs * g0.x + b0.x;
    float o1 = (a.y - mean) * rs * g0.y + b0.y;
    float o2 = (a.z - mean) * rs * g0.z + b0.z;
    float o3 = (a.w - mean) * rs * g0.w + b0.w;
    float o4 = (b.x - mean) * rs * g1.x + b1.x;
    float o5 = (b.y - mean) * rs * g1.y + b1.y;
    float o6 = (b.z - mean) * rs * g1.z + b1.z;
    float o7 = (b.w - mean) * rs * g1.w + b1.w;
    __nv_bfloat162 r0 = __floats2bfloat162_rn(o0, o1);
    __nv_bfloat162 r1 = __floats2bfloat162_rn(o2, o3);
    __nv_bfloat162 r2 = __floats2bfloat162_rn(o4, o5);
    __nv_bfloat162 r3 = __floats2bfloat162_rn(o6, o7);
    uint4 u;
    u.x = *(unsigned int*)&r0; u.y = *(unsigned int*)&r1;
    u.z = *(unsigned int*)&r2; u.w = *(unsigned int*)&r3;
    ((uint4*)(out + (size_t)row * CC))[lane] = u;
}

// =====================================================================
// prep kernel: LN1 + pack_proj + pack_other in one launch
// =====================================================================
#define LN_BLOCKS   (MM / 8)                          // 1280
#define PACK_PROJ_TOTAL (CC * NPROJ + NPROJ)          // 559232
#define PP_BLOCKS   ((PACK_PROJ_TOTAL + 255) / 256)   // 2185
#define PACK_OTHER_TOTAL (CC*CC + CC*MLPH + MLPH*CC)  // 589824
#define PO_BLOCKS   ((PACK_OTHER_TOTAL + 255) / 256)  // 2304
#define PREP_BLOCKS (LN_BLOCKS + PP_BLOCKS + PO_BLOCKS)

__global__ void prep_kernel(const float* __restrict__ x,
                            const float* __restrict__ n3g,
                            const float* __restrict__ n3b,
                            const float* __restrict__ wv,
                            const float* __restrict__ wo,
                            const float* __restrict__ wa,
                            const float* __restrict__ bv,
                            const float* __restrict__ bo,
                            const float* __restrict__ ba,
                            const float* __restrict__ wout,
                            const float* __restrict__ wf1,
                            const float* __restrict__ wf2) {
    int bid = blockIdx.x;
    if (bid < LN_BLOCKS) {
        int warp = threadIdx.x >> 5, lane = threadIdx.x & 31;
        ln_row(x, n3g, n3b, g_q, bid * 8 + warp, lane);
        return;
    }
    if (bid < LN_BLOCKS + PP_BLOCKS) {
        int i = (bid - LN_BLOCKS) * 256 + threadIdx.x;
        if (i >= PACK_PROJ_TOTAL) return;
        if (i < CC * NPROJ) {
            int k = i / NPROJ, j = i - k * NPROJ;
            float v;
            if (j < 256)        v = wv[k * 256 + j];
            else if (j < 1536)  v = wo[k * 1280 + (j - 256)];
            else                v = wa[k * 640 + (j - 1536)];
            g_w_proj[i] = __float2bfloat16(v);
            return;
        }
        i -= CC * NPROJ;
        float v;
        if (i < 256)        v = bv[i];
        else if (i < 1536)  v = bo[i - 256];
        else                v = ba[i - 1536];
        g_b_proj[i] = v;
        return;
    }
    int i = (bid - LN_BLOCKS - PP_BLOCKS) * 256 + threadIdx.x;
    if (i < CC * CC) { g_w_out[i] = __float2bfloat16(wout[i]); return; }
    i -= CC * CC;
    if (i < CC * MLPH) { g_w_fc1[i] = __float2bfloat16(wf1[i]); return; }
    i -= CC * MLPH;
    if (i < MLPH * CC) g_w_fc2[i] = __float2bfloat16(wf2[i]);
}

// standalone LN (for ln2)
__global__ void ln_kernel(const float* __restrict__ x,
                          const float* __restrict__ gam,
                          const float* __restrict__ bet,
                          __nv_bfloat16* __restrict__ out) {
    ln_row(x, gam, bet, out, blockIdx.x * 8 + (threadIdx.x >> 5), threadIdx.x & 31);
}

// =====================================================================
// bf16 WMMA GEMM v5 (proven): block 128x128, 8 warps (4x2) of 32x64,
// K-step 64, 2-stage cp.async.  Used for proj (projmode) and fc1.
// =====================================================================
#define GSTAGE 35840
#define GSMEM  (2 * GSTAGE)

__global__ void gemm_bf16_kernel(const __nv_bfloat16* __restrict__ A,
                                 const __nv_bfloat16* __restrict__ Bw,
                                 const float* __restrict__ bias,
                                 const float* __restrict__ resid,
                                 float* __restrict__ out_f32,
                                 __nv_bfloat16* __restrict__ out_bf16,
                                 int M, int N, int K, int act, int projmode) {
    extern __shared__ __align__(16) unsigned char smem_raw[];

    int bm = blockIdx.y, bn = blockIdx.x;
    int tid = threadIdx.x;
    int w  = tid >> 5, lane = tid & 31;
    int wm = w >> 1, wn = w & 1;

    wmma::fragment<wmma::accumulator, 16, 16, 16, float> cf[2][4];
#pragma unroll
    for (int i = 0; i < 2; ++i)
#pragma unroll
        for (int j = 0; j < 4; ++j)
            wmma::fill_fragment(cf[i][j], 0.0f);

    const int steps = K >> 6;

    auto issue = [&](int buf, int k0) {
        __nv_bfloat16* sa = (__nv_bfloat16*)(smem_raw + buf * GSTAGE);
        __nv_bfloat16* sb = (__nv_bfloat16*)(smem_raw + buf * GSTAGE + 18432);
#pragma unroll
        for (int u0 = 0; u0 < 4; ++u0) {
            int c = tid + u0 * 256;
            int row = c >> 3, c8 = (c & 7) << 3;
            unsigned dst = (unsigned)__cvta_generic_to_shared(sa + row * 72 + c8);
            CP16(dst, A + (size_t)(bm * 128 + row) * K + k0 + c8);
        }
#pragma unroll
        for (int u0 = 0; u0 < 4; ++u0) {
            int c = tid + u0 * 256;
            int row = c >> 4, c8 = (c & 15) << 3;
            unsigned dst = (unsigned)__cvta_generic_to_shared(sb + row * 136 + c8);
            CP16(dst, Bw + (size_t)(k0 + row) * N + bn * 128 + c8);
        }
    };

    issue(0, 0); CP_COMMIT();

    for (int s = 0; s < steps; ++s) {
        int cur = s & 1;
        if (s + 1 < steps) { issue((s + 1) & 1, (s + 1) << 6); CP_COMMIT(); CP_WAIT1(); }
        else               { CP_WAIT0(); }
        __syncthreads();

        __nv_bfloat16* sa = (__nv_bfloat16*)(smem_raw + cur * GSTAGE);
        __nv_bfloat16* sb = (__nv_bfloat16*)(smem_raw + cur * GSTAGE + 18432);
#pragma unroll
        for (int kk = 0; kk < 64; kk += 16) {
            wmma::fragment<wmma::matrix_a, 16, 16, 16, __nv_bfloat16, wmma::row_major> af[2];
            wmma::fragment<wmma::matrix_b, 16, 16, 16, __nv_bfloat16, wmma::row_major> bf[4];
#pragma unroll
            for (int i = 0; i < 2; ++i)
                wmma::load_matrix_sync(af[i], sa + (wm * 32 + i * 16) * 72 + kk, 72);
#pragma unroll
            for (int j = 0; j < 4; ++j)
                wmma::load_matrix_sync(bf[j], sb + kk * 136 + wn * 64 + j * 16, 136);
#pragma unroll
            for (int i = 0; i < 2; ++i)
#pragma unroll
                for (int j = 0; j < 4; ++j)
                    wmma::mma_sync(cf[i][j], af[i], bf[j], cf[i][j]);
        }
        __syncthreads();
    }

    float* stage = (float*)smem_raw + w * 1152;
#pragma unroll
    for (int jh = 0; jh < 2; ++jh) {
        __syncwarp();
#pragma unroll
        for (int i = 0; i < 2; ++i)
#pragma unroll
            for (int j = 0; j < 2; ++j)
                wmma::store_matrix_sync(stage + (i * 16) * 36 + j * 16,
                                        cf[i][jh * 2 + j], 36, wmma::mem_row_major);
        __syncwarp();
#pragma unroll
        for (int it = 0; it < 32; ++it) {
            float v = stage[it * 36 + lane];
            int grow = bm * 128 + wm * 32 + it;
            int gcol = bn * 128 + wn * 64 + jh * 32 + lane;
            if (projmode) {
                v += g_b_proj[gcol];
                if (gcol < 256) {
                    int b = grow / LQQ;
                    int rem = grow - b * LQQ;
                    int l = rem >> 10, yx = rem & 1023;
                    int h = gcol >> 5, d = gcol & 31;
                    g_vperm[((((b * NHH + h) * NLL + l) << 10) + yx) * HDD + d] =
                        __float2bfloat16(v);
                } else if (gcol < 1536) {
                    g_off[(size_t)grow * 1280 + (gcol - 256)] = v;
                } else {
                    g_aw[(size_t)grow * 640 + (gcol - 1536)] = v;
                }
            } else {
                v += bias[gcol];
                if (act) v = 0.5f * v * (1.0f + erff(v * 0.70710678118654752f));
                if (resid) v += resid[(size_t)grow * N + gcol];
                if (out_f32) out_f32[(size_t)grow * N + gcol] = v;
                if (out_bf16) out_bf16[(size_t)grow * N + gcol] = __float2bfloat16(v);
            }
        }
    }
}

// =====================================================================
// bf16 WMMA GEMM n64: block 128(M) x 64(N), 8 warps of 16x64 (cf[4]),
// K-step 64, 2-stage cp.async.  For grid-limited tail GEMMs (out, fc2).
// B tile: 64 rows x 64 cols (8 x 16B chunks per row) -> row=c>>3.
// Stage: A 128x72 (18432B) + B 64x72 (9216B) = 27648B; x2 = 55296B.
// =====================================================================
#define NSTAGE 27648
#define NSMEM  (2 * NSTAGE)

__global__ void gemm_n64_kernel(const __nv_bfloat16* __restrict__ A,
                                const __nv_bfloat16* __restrict__ Bw,
                                const float* __restrict__ bias,
                                const float* __restrict__ resid,
                                float* __restrict__ out_f32,
                                int M, int N, int K) {
    extern __shared__ __align__(16) unsigned char smem_raw[];

    int bm = blockIdx.y, bn = blockIdx.x;
    int tid = threadIdx.x;
    int w  = tid >> 5, lane = tid & 31;

    wmma::fragment<wmma::accumulator, 16, 16, 16, float> cf[4];
#pragma unroll
    for (int j = 0; j < 4; ++j)
        wmma::fill_fragment(cf[j], 0.0f);

    const int steps = K >> 6;

    auto issue = [&](int buf, int k0) {
        __nv_bfloat16* sa = (__nv_bfloat16*)(smem_raw + buf * NSTAGE);
        __nv_bfloat16* sb = (__nv_bfloat16*)(smem_raw + buf * NSTAGE + 18432);
#pragma unroll
        for (int u0 = 0; u0 < 4; ++u0) {        // A: 1024 x 16B (128 rows x 64 cols)
            int c = tid + u0 * 256;
            int row = c >> 3, c8 = (c & 7) << 3;
            unsigned dst = (unsigned)__cvta_generic_to_shared(sa + row * 72 + c8);
            CP16(dst, A + (size_t)(bm * 128 + row) * K + k0 + c8);
        }
#pragma unroll
        for (int u0 = 0; u0 < 2; ++u0) {        // B: 512 x 16B (64 rows x 64 cols)
            int c = tid + u0 * 256;
            int row = c >> 3, c8 = (c & 7) << 3;
            unsigned dst = (unsigned)__cvta_generic_to_shared(sb + row * 72 + c8);
            CP16(dst, Bw + (size_t)(k0 + row) * N + bn * 64 + c8);
        }
    };

    issue(0, 0); CP_COMMIT();

    for (int s = 0; s < steps; ++s) {
        int cur = s & 1;
        if (s + 1 < steps) { issue((s + 1) & 1, (s + 1) << 6); CP_COMMIT(); CP_WAIT1(); }
        else               { CP_WAIT0(); }
        __syncthreads();

        __nv_bfloat16* sa = (__nv_bfloat16*)(smem_raw + cur * NSTAGE);
        __nv_bfloat16* sb = (__nv_bfloat16*)(smem_raw + cur * NSTAGE + 18432);
#pragma unroll
        for (int kk = 0; kk < 64; kk += 16) {
            wmma::fragment<wmma::matrix_a, 16, 16, 16, __nv_bfloat16, wmma::row_major> af;
            wmma::fragment<wmma::matrix_b, 16, 16, 16, __nv_bfloat16, wmma::row_major> bf[4];
            wmma::load_matrix_sync(af, sa + (w * 16) * 72 + kk, 72);
#pragma unroll
            for (int j = 0; j < 4; ++j)
                wmma::load_matrix_sync(bf[j], sb + kk * 72 + j * 16, 72);
#pragma unroll
            for (int j = 0; j < 4; ++j)
                wmma::mma_sync(cf[j], af, bf[j], cf[j]);
        }
        __syncthreads();
    }

    // per-warp staged epilogue: two 16x32 passes, stage stride 36
    float* stage = (float*)smem_raw + w * 576;    // 16*36 floats = 2304B/warp
#pragma unroll
    for (int jh = 0; jh < 2; ++jh) {
        __syncwarp();
#pragma unroll
        for (int j = 0; j < 2; ++j)
            wmma::store_matrix_sync(stage + j * 16, cf[jh * 2 + j], 36,
                                    wmma::mem_row_major);
        __syncwarp();
#pragma unroll
        for (int it = 0; it < 16; ++it) {
            float v = stage[it * 36 + lane];
            int grow = bm * 128 + w * 16 + it;
            int gcol = bn * 64 + jh * 32 + lane;
            v += bias[gcol];
            if (resid) v += resid[(size_t)grow * N + gcol];
            out_f32[(size_t)grow * N + gcol] = v;
        }
    }
}

// =====================================================================
// deformable sampling v4: two-phase + packed f32x2 accumulation
// =====================================================================
#define FFMA2(acc, v, w) \
    asm("fma.rn.f32x2 %0, %1, %2, %0;" : "+l"(acc) : "l"(v), "l"(w))

__global__ void sample_kernel(const float* __restrict__ refpts) {
    int warp = threadIdx.x >> 5, lane = threadIdx.x & 31;
    int unit = blockIdx.x * 8 + warp;                // 81920 units
    int token = unit >> 3;
    int h = unit & 7;
    int b = token / LQQ;

    __shared__ float s_aw[8][80];
    __shared__ float s_ref[8][10];
    __shared__ __align__(16) float s_wo[8][80 * 8];

    const float* awp = g_aw + (size_t)token * 640 + h * 80;
    for (int i = lane; i < 80; i += 32) s_aw[warp][i] = awp[i];
    const float* rp = refpts + (size_t)token * 10;
    if (lane < 10) s_ref[warp][lane] = rp[lane];
    __syncwarp();

    {
        float v0 = s_aw[warp][lane];
        float v1 = s_aw[warp][lane + 32];
        float v2 = (lane < 16) ? s_aw[warp][lane + 64] : -1e30f;
        float m = fmaxf(fmaxf(v0, v1), v2);
#pragma unroll
        for (int o = 16; o > 0; o >>= 1) m = fmaxf(m, __shfl_xor_sync(0xffffffffu, m, o));
        float e0 = expf(v0 - m), e1 = expf(v1 - m);
        float e2 = (lane < 16) ? expf(v2 - m) : 0.0f;
        float s = e0 + e1 + e2;
#pragma unroll
        for (int o = 16; o > 0; o >>= 1) s += __shfl_xor_sync(0xffffffffu, s, o);
        float inv = 1.0f / s;
        s_aw[warp][lane] = e0 * inv;
        s_aw[warp][lane + 32] = e1 * inv;
        if (lane < 16) s_aw[warp][lane + 64] = e2 * inv;
        __syncwarp();
    }

    const float2* offp = (const float2*)(g_off + (size_t)token * 1280 + h * 160);
#pragma unroll
    for (int si = lane; si < 80; si += 32) {
        int l = si >> 4;
        float2 of = offp[si];
        float px = s_ref[warp][l * 2 + 0] * 32.0f - 0.5f + of.x;
        float py = s_ref[warp][l * 2 + 1] * 32.0f - 0.5f + of.y;
        float a  = s_aw[warp][si];
        float fx0 = floorf(px), fy0 = floorf(py);
        float fx = px - fx0, fy = py - fy0;
        int x0 = (int)fx0, y0 = (int)fy0;
        int lbase = l << 16;
        float4 pk0, pk1;
        {
            bool ok = (x0 >= 0) && (x0 < 32) && (y0 >= 0) && (y0 < 32);
            int xc = min(max(x0, 0), 31), yc = min(max(y0, 0), 31);
            pk0.x = ok ? a * (1.0f - fx) * (1.0f - fy) : 0.0f;
            pk0.y = __int_as_float(lbase + (((yc << 5) + xc) << 6));
        }
        {
            int xi = x0 + 1;
            bool ok = (xi >= 0) && (xi < 32) && (y0 >= 0) && (y0 < 32);
            int xc = min(max(xi, 0), 31), yc = min(max(y0, 0), 31);
            pk0.z = ok ? a * fx * (1.0f - fy) : 0.0f;
            pk0.w = __int_as_float(lbase + (((yc << 5) + xc) << 6));
        }
        {
            int yi = y0 + 1;
            bool ok = (x0 >= 0) && (x0 < 32) && (yi >= 0) && (yi < 32);
            int xc = min(max(x0, 0), 31), yc = min(max(yi, 0), 31);
            pk1.x = ok ? a * (1.0f - fx) * fy : 0.0f;
            pk1.y = __int_as_float(lbase + (((yc << 5) + xc) << 6));
        }
        {
            int xi = x0 + 1, yi = y0 + 1;
            bool ok = (xi >= 0) && (xi < 32) && (yi >= 0) && (yi < 32);
            int xc = min(max(xi, 0), 31), yc = min(max(yi, 0), 31);
            pk1.z = ok ? a * fx * fy : 0.0f;
            pk1.w = __int_as_float(lbase + (((yc << 5) + xc) << 6));
        }
        *(float4*)&s_wo[warp][si * 8]     = pk0;
        *(float4*)&s_wo[warp][si * 8 + 4] = pk1;
    }
    __syncwarp();

    int q    = lane & 3;
    int tap  = (lane >> 2) & 3;
    int sgrp = lane >> 4;
    const float* wo = &s_wo[warp][tap * 2];
    const char* vbase = (const char*)
        (g_vperm + ((size_t)((b * NHH + h) * NLL) << 15) + (q << 3));

    uint64_t a0 = 0, a1 = 0, a2 = 0, a3 = 0;

#pragma unroll 8
    for (int r = 0; r < 40; ++r) {
        int s = r * 2 + sgrp;
        float2 p = *(const float2*)(wo + s * 8);
        uint32_t wb = __float_as_uint(p.x);
        uint64_t wpk;
        asm("mov.b64 %0, {%1, %2};" : "=l"(wpk) : "r"(wb), "r"(wb));
        uint4 u = *(const uint4*)(vbase + __float_as_int(p.y));
        uint64_t v;
        uint32_t lo, hi;
        lo = u.x << 16; hi = u.x & 0xFFFF0000u;
        asm("mov.b64 %0, {%1, %2};" : "=l"(v) : "r"(lo), "r"(hi));
        FFMA2(a0, v, wpk);
        lo = u.y << 16; hi = u.y & 0xFFFF0000u;
        asm("mov.b64 %0, {%1, %2};" : "=l"(v) : "r"(lo), "r"(hi));
        FFMA2(a1, v, wpk);
        lo = u.z << 16; hi = u.z & 0xFFFF0000u;
        asm("mov.b64 %0, {%1, %2};" : "=l"(v) : "r"(lo), "r"(hi));
        FFMA2(a2, v, wpk);
        lo = u.w << 16; hi = u.w & 0xFFFF0000u;
        asm("mov.b64 %0, {%1, %2};" : "=l"(v) : "r"(lo), "r"(hi));
        FFMA2(a3, v, wpk);
    }

    float2 acc0, acc1, acc2, acc3;
    {
        uint32_t lo, hi;
        asm("mov.b64 {%0, %1}, %2;" : "=r"(lo), "=r"(hi) : "l"(a0));
        acc0.x = __uint_as_float(lo); acc0.y = __uint_as_float(hi);
        asm("mov.b64 {%0, %1}, %2;" : "=r"(lo), "=r"(hi) : "l"(a1));
        acc1.x = __uint_as_float(lo); acc1.y = __uint_as_float(hi);
        asm("mov.b64 {%0, %1}, %2;" : "=r"(lo), "=r"(hi) : "l"(a2));
        acc2.x = __uint_as_float(lo); acc2.y = __uint_as_float(hi);
        asm("mov.b64 {%0, %1}, %2;" : "=r"(lo), "=r"(hi) : "l"(a3));
        acc3.x = __uint_as_float(lo); acc3.y = __uint_as_float(hi);
    }

#pragma unroll
    for (int o = 4; o <= 16; o <<= 1) {
        acc0.x += __shfl_xor_sync(0xffffffffu, acc0.x, o);
        acc0.y += __shfl_xor_sync(0xffffffffu, acc0.y, o);
        acc1.x += __shfl_xor_sync(0xffffffffu, acc1.x, o);
        acc1.y += __shfl_xor_sync(0xffffffffu, acc1.y, o);
        acc2.x += __shfl_xor_sync(0xffffffffu, acc2.x, o);
        acc2.y += __shfl_xor_sync(0xffffffffu, acc2.y, o);
        acc3.x += __shfl_xor_sync(0xffffffffu, acc3.x, o);
        acc3.y += __shfl_xor_sync(0xffffffffu, acc3.y, o);
    }

    if (lane < 4) {
        __nv_bfloat162 r0 = __floats2bfloat162_rn(acc0.x, acc0.y);
        __nv_bfloat162 r1 = __floats2bfloat162_rn(acc1.x, acc1.y);
        __nv_bfloat162 r2 = __floats2bfloat162_rn(acc2.x, acc2.y);
        __nv_bfloat162 r3 = __floats2bfloat162_rn(acc3.x, acc3.y);
        uint4 o;
        o.x = *(unsigned int*)&r0; o.y = *(unsigned int*)&r1;
        o.z = *(unsigned int*)&r2; o.w = *(unsigned int*)&r3;
        ((uint4*)(g_samp + (size_t)token * CC + h * 32))[q] = o;
    }
}

// =====================================================================
// launch
// =====================================================================
extern "C" void kernel_launch(void* const* d_in, const int* in_sizes, int n_in,
                              void* d_out, int out_size) {
    const float* x      = (const float*)d_in[0];
    const float* refpts = (const float*)d_in[1];
    const float* n3g = (const float*)d_in[4];
    const float* n3b = (const float*)d_in[5];
    const float* n4g = (const float*)d_in[6];
    const float* n4b = (const float*)d_in[7];
    const float* w_off  = (const float*)d_in[8];
    const float* b_off  = (const float*)d_in[9];
    const float* w_attn = (const float*)d_in[10];
    const float* b_attn = (const float*)d_in[11];
    const float* w_val  = (const float*)d_in[12];
    const float* b_val  = (const float*)d_in[13];
    const float* w_out  = (const float*)d_in[14];
    const float* b_out  = (const float*)d_in[15];
    const float* w_fc1  = (const float*)d_in[16];
    const float* b_fc1  = (const float*)d_in[17];
    const float* w_fc2  = (const float*)d_in[18];
    const float* b_fc2  = (const float*)d_in[19];
    float* outp = (float*)d_out;

    void *p_q, *p_hln, *p_samp, *p_mh, *p_x1;
    void *p_wp, *p_wou, *p_wf1, *p_wf2;
    cudaGetSymbolAddress(&p_q, g_q);
    cudaGetSymbolAddress(&p_hln, g_hln);
    cudaGetSymbolAddress(&p_samp, g_samp);
    cudaGetSymbolAddress(&p_mh, g_mh);
    cudaGetSymbolAddress(&p_x1, g_x1);
    cudaGetSymbolAddress(&p_wp, g_w_proj);
    cudaGetSymbolAddress(&p_wou, g_w_out);
    cudaGetSymbolAddress(&p_wf1, g_w_fc1);
    cudaGetSymbolAddress(&p_wf2, g_w_fc2);

    cudaFuncSetAttribute(gemm_bf16_kernel,
                         cudaFuncAttributeMaxDynamicSharedMemorySize, GSMEM);
    cudaFuncSetAttribute(gemm_n64_kernel,
                         cudaFuncAttributeMaxDynamicSharedMemorySize, NSMEM);

    // 1. prep: LN1 + all weight packing (one launch, independent work)
    prep_kernel<<<PREP_BLOCKS, 256>>>(x, n3g, n3b,
                                      w_val, w_off, w_attn, b_val, b_off, b_attn,
                                      w_out, w_fc1, w_fc2);

    // 2. fused projection GEMM (val->vperm, off, attn) N=2176
    gemm_bf16_kernel<<<dim3(NPROJ / 128, MM / 128), 256, GSMEM>>>(
        (const __nv_bfloat16*)p_q, (const __nv_bfloat16*)p_wp, nullptr,
        nullptr, nullptr, nullptr, MM, NPROJ, CC, 0, 1);

    // 3. deformable sampling v4 (+fused softmax) -> g_samp
    sample_kernel<<<MM * NHH / 8, 256>>>(refpts);

    // 4. out-proj + residual(x) -> x1 (f32)   [n64: grid 320]
    gemm_n64_kernel<<<dim3(CC / 64, MM / 128), 256, NSMEM>>>(
        (const __nv_bfloat16*)p_samp, (const __nv_bfloat16*)p_wou, b_out,
        x, (float*)p_x1, MM, CC, CC);

    // 5. h = LN(x1) (bf16)
    ln_kernel<<<MM / 8, 256>>>((const float*)p_x1, n4g, n4b, (__nv_bfloat16*)p_hln);

    // 6. fc1 + GELU -> mh (bf16)
    gemm_bf16_kernel<<<dim3(MLPH / 128, MM / 128), 256, GSMEM>>>(
        (const __nv_bfloat16*)p_hln, (const __nv_bfloat16*)p_wf1, b_fc1,
        nullptr, nullptr, (__nv_bfloat16*)p_mh, MM, MLPH, CC, 1, 0);

    // 7. fc2 + residual(x1) -> d_out (f32)   [n64: grid 320]
    gemm_n64_kernel<<<dim3(CC / 64, MM / 128), 256, NSMEM>>>(
        (const __nv_bfloat16*)p_mh, (const __nv_bfloat16*)p_wf2, b_fc2,
        (const float*)p_x1, outp, MM, CC, MLPH);
}

// round 17
// speedup vs baseline: 1.0479x; 1.0479x over previous
#include <cuda_runtime.h>
#include <cuda_bf16.h>
#include <mma.h>
#include <cstdint>

using namespace nvcuda;

// ---- problem constants ----
#define BD   2
#define CC   256
#define NHH  8
#define NLL  5
#define NPP  16
#define HDD  32
#define MLPH 1024
#define HWW  1024
#define LQQ  5120
#define MM   10240     // B * LQ tokens
#define NPROJ 2176     // 256 + 1280 + 640

// ---- scratch (device globals; no runtime allocation allowed) ----
__device__ __align__(256) __nv_bfloat16 g_q[MM * CC];
__device__ __align__(256) __nv_bfloat16 g_hln[MM * CC];
__device__ __align__(256) __nv_bfloat16 g_samp[MM * CC];
__device__ __align__(256) __nv_bfloat16 g_mh[MM * MLPH];
__device__ __align__(256) __nv_bfloat16 g_vperm[BD * NHH * NLL * HWW * HDD];
__device__ __align__(256) float g_off[MM * 1280];
__device__ __align__(256) float g_aw[MM * 640];
__device__ __align__(256) float g_x1[MM * CC];
__device__ __align__(256) __nv_bfloat16 g_w_proj[CC * NPROJ];
__device__ __align__(256) float g_b_proj[NPROJ];
__device__ __align__(256) __nv_bfloat16 g_w_out[CC * CC];
__device__ __align__(256) __nv_bfloat16 g_w_fc1[CC * MLPH];
__device__ __align__(256) __nv_bfloat16 g_w_fc2[MLPH * CC];

// cp.async helpers
#define CP16(dst, src) \
    asm volatile("cp.async.cg.shared.global [%0], [%1], 16;" :: "r"(dst), "l"(src))
#define CP_COMMIT() asm volatile("cp.async.commit_group;" ::: "memory")
#define CP_WAIT1()  asm volatile("cp.async.wait_group 1;" ::: "memory")
#define CP_WAIT0()  asm volatile("cp.async.wait_group 0;" ::: "memory")

// =====================================================================
// LN body (shared)
// =====================================================================
__device__ __forceinline__ void ln_row(const float* __restrict__ x,
                                       const float* __restrict__ gam,
                                       const float* __restrict__ bet,
                                       __nv_bfloat16* __restrict__ out,
                                       int row, int lane) {
    const float4* xp = (const float4*)(x + (size_t)row * CC);
    float4 a = xp[lane * 2];
    float4 b = xp[lane * 2 + 1];
    float s  = a.x + a.y + a.z + a.w + b.x + b.y + b.z + b.w;
    float sq = a.x*a.x + a.y*a.y + a.z*a.z + a.w*a.w
             + b.x*b.x + b.y*b.y + b.z*b.z + b.w*b.w;
#pragma unroll
    for (int o = 16; o > 0; o >>= 1) {
        s  += __shfl_xor_sync(0xffffffffu, s,  o);
        sq += __shfl_xor_sync(0xffffffffu, sq, o);
    }
    float mean = s * (1.0f / CC);
    float var  = sq * (1.0f / CC) - mean * mean;
    float rs   = rsqrtf(var + 1e-5f);
    const float4* gp = (const float4*)gam;
    const float4* bp = (const float4*)bet;
    float4 g0 = gp[lane * 2], g1 = gp[lane * 2 + 1];
    float4 b0 = bp[lane * 2], b1 = bp[lane * 2 + 1];
    float o0 = (a.x - mean) * rs * g0.x + b0.x;
    float o1 = (a.y - mean) * rs * g0.y + b0.y;
    float o2 = (a.z - mean) * rs * g0.z + b0.z;
    float o3 = (a.w - mean) * rs * g0.w + b0.w;
    float o4 = (b.x - mean) * rs * g1.x + b1.x;
    float o5 = (b.y - mean) * rs * g1.y + b1.y;
    float o6 = (b.z - mean) * rs * g1.z + b1.z;
    float o7 = (b.w - mean) * rs * g1.w + b1.w;
    __nv_bfloat162 r0 = __floats2bfloat162_rn(o0, o1);
    __nv_bfloat162 r1 = __floats2bfloat162_rn(o2, o3);
    __nv_bfloat162 r2 = __floats2bfloat162_rn(o4, o5);
    __nv_bfloat162 r3 = __floats2bfloat162_rn(o6, o7);
    uint4 u;
    u.x = *(unsigned int*)&r0; u.y = *(unsigned int*)&r1;
    u.z = *(unsigned int*)&r2; u.w = *(unsigned int*)&r3;
    ((uint4*)(out + (size_t)row * CC))[lane] = u;
}

// =====================================================================
// prep kernel: LN1 + pack_proj + pack_other in one launch
// =====================================================================
#define LN_BLOCKS   (MM / 8)                          // 1280
#define PACK_PROJ_TOTAL (CC * NPROJ + NPROJ)          // 559232
#define PP_BLOCKS   ((PACK_PROJ_TOTAL + 255) / 256)   // 2185
#define PACK_OTHER_TOTAL (CC*CC + CC*MLPH + MLPH*CC)  // 589824
#define PO_BLOCKS   ((PACK_OTHER_TOTAL + 255) / 256)  // 2304
#define PREP_BLOCKS (LN_BLOCKS + PP_BLOCKS + PO_BLOCKS)

__global__ void prep_kernel(const float* __restrict__ x,
                            const float* __restrict__ n3g,
                            const float* __restrict__ n3b,
                            const float* __restrict__ wv,
                            const float* __restrict__ wo,
                            const float* __restrict__ wa,
                            const float* __restrict__ bv,
                            const float* __restrict__ bo,
                            const float* __restrict__ ba,
                            const float* __restrict__ wout,
                            const float* __restrict__ wf1,
                            const float* __restrict__ wf2) {
    int bid = blockIdx.x;
    if (bid < LN_BLOCKS) {
        int warp = threadIdx.x >> 5, lane = threadIdx.x & 31;
        ln_row(x, n3g, n3b, g_q, bid * 8 + warp, lane);
        return;
    }
    if (bid < LN_BLOCKS + PP_BLOCKS) {
        int i = (bid - LN_BLOCKS) * 256 + threadIdx.x;
        if (i >= PACK_PROJ_TOTAL) return;
        if (i < CC * NPROJ) {
            int k = i / NPROJ, j = i - k * NPROJ;
            float v;
            if (j < 256)        v = wv[k * 256 + j];
            else if (j < 1536)  v = wo[k * 1280 + (j - 256)];
            else                v = wa[k * 640 + (j - 1536)];
            g_w_proj[i] = __float2bfloat16(v);
            return;
        }
        i -= CC * NPROJ;
        float v;
        if (i < 256)        v = bv[i];
        else if (i < 1536)  v = bo[i - 256];
        else                v = ba[i - 1536];
        g_b_proj[i] = v;
        return;
    }
    int i = (bid - LN_BLOCKS - PP_BLOCKS) * 256 + threadIdx.x;
    if (i < CC * CC) { g_w_out[i] = __float2bfloat16(wout[i]); return; }
    i -= CC * CC;
    if (i < CC * MLPH) { g_w_fc1[i] = __float2bfloat16(wf1[i]); return; }
    i -= CC * MLPH;
    if (i < MLPH * CC) g_w_fc2[i] = __float2bfloat16(wf2[i]);
}

// standalone LN (for ln2)
__global__ void ln_kernel(const float* __restrict__ x,
                          const float* __restrict__ gam,
                          const float* __restrict__ bet,
                          __nv_bfloat16* __restrict__ out) {
    ln_row(x, gam, bet, out, blockIdx.x * 8 + (threadIdx.x >> 5), threadIdx.x & 31);
}

// =====================================================================
// bf16 WMMA GEMM v5 (proven): block 128x128, 8 warps (4x2) of 32x64,
// K-step 64, 2-stage cp.async double buffer, bf[4] array loads.
// Stage: A 128x72 bf16 (18432B) + B 64x136 bf16 (17408B) = 35840B.
// Per-warp staged epilogue, stage stride 36 floats.
// projmode=1: fused projection epilogue (val->vperm bf16, off/attn->f32)
// =====================================================================
#define GSTAGE 35840
#define GSMEM  (2 * GSTAGE)

__global__ void gemm_bf16_kernel(const __nv_bfloat16* __restrict__ A,
                                 const __nv_bfloat16* __restrict__ Bw,
                                 const float* __restrict__ bias,
                                 const float* __restrict__ resid,
                                 float* __restrict__ out_f32,
                                 __nv_bfloat16* __restrict__ out_bf16,
                                 int M, int N, int K, int act, int projmode) {
    extern __shared__ __align__(16) unsigned char smem_raw[];

    int bm = blockIdx.y, bn = blockIdx.x;
    int tid = threadIdx.x;
    int w  = tid >> 5, lane = tid & 31;
    int wm = w >> 1, wn = w & 1;          // 4x2 warps, each 32(M) x 64(N)

    wmma::fragment<wmma::accumulator, 16, 16, 16, float> cf[2][4];
#pragma unroll
    for (int i = 0; i < 2; ++i)
#pragma unroll
        for (int j = 0; j < 4; ++j)
            wmma::fill_fragment(cf[i][j], 0.0f);

    const int steps = K >> 6;             // K-step 64

    auto issue = [&](int buf, int k0) {
        __nv_bfloat16* sa = (__nv_bfloat16*)(smem_raw + buf * GSTAGE);
        __nv_bfloat16* sb = (__nv_bfloat16*)(smem_raw + buf * GSTAGE + 18432);
#pragma unroll
        for (int u0 = 0; u0 < 4; ++u0) {        // A: 1024 x 16B (128 x 64)
            int c = tid + u0 * 256;
            int row = c >> 3, c8 = (c & 7) << 3;
            unsigned dst = (unsigned)__cvta_generic_to_shared(sa + row * 72 + c8);
            CP16(dst, A + (size_t)(bm * 128 + row) * K + k0 + c8);
        }
#pragma unroll
        for (int u0 = 0; u0 < 4; ++u0) {        // B: 1024 x 16B (64 x 128)
            int c = tid + u0 * 256;
            int row = c >> 4, c8 = (c & 15) << 3;
            unsigned dst = (unsigned)__cvta_generic_to_shared(sb + row * 136 + c8);
            CP16(dst, Bw + (size_t)(k0 + row) * N + bn * 128 + c8);
        }
    };

    issue(0, 0); CP_COMMIT();

    for (int s = 0; s < steps; ++s) {
        int cur = s & 1;
        if (s + 1 < steps) { issue((s + 1) & 1, (s + 1) << 6); CP_COMMIT(); CP_WAIT1(); }
        else               { CP_WAIT0(); }
        __syncthreads();

        __nv_bfloat16* sa = (__nv_bfloat16*)(smem_raw + cur * GSTAGE);
        __nv_bfloat16* sb = (__nv_bfloat16*)(smem_raw + cur * GSTAGE + 18432);
#pragma unroll
        for (int kk = 0; kk < 64; kk += 16) {
            wmma::fragment<wmma::matrix_a, 16, 16, 16, __nv_bfloat16, wmma::row_major> af[2];
            wmma::fragment<wmma::matrix_b, 16, 16, 16, __nv_bfloat16, wmma::row_major> bf[4];
#pragma unroll
            for (int i = 0; i < 2; ++i)
                wmma::load_matrix_sync(af[i], sa + (wm * 32 + i * 16) * 72 + kk, 72);
#pragma unroll
            for (int j = 0; j < 4; ++j)
                wmma::load_matrix_sync(bf[j], sb + kk * 136 + wn * 64 + j * 16, 136);
#pragma unroll
            for (int i = 0; i < 2; ++i)
#pragma unroll
                for (int j = 0; j < 4; ++j)
                    wmma::mma_sync(cf[i][j], af[i], bf[j], cf[i][j]);
        }
        __syncthreads();
    }

    // per-warp staged epilogue: two 32x32 passes, stage stride 36 (16B mult)
    float* stage = (float*)smem_raw + w * 1152;   // 32*36 floats = 4608B/warp
#pragma unroll
    for (int jh = 0; jh < 2; ++jh) {
        __syncwarp();
#pragma unroll
        for (int i = 0; i < 2; ++i)
#pragma unroll
            for (int j = 0; j < 2; ++j)
                wmma::store_matrix_sync(stage + (i * 16) * 36 + j * 16,
                                        cf[i][jh * 2 + j], 36, wmma::mem_row_major);
        __syncwarp();
#pragma unroll
        for (int it = 0; it < 32; ++it) {
            float v = stage[it * 36 + lane];
            int grow = bm * 128 + wm * 32 + it;
            int gcol = bn * 128 + wn * 64 + jh * 32 + lane;
            if (projmode) {
                v += g_b_proj[gcol];
                if (gcol < 256) {
                    int b = grow / LQQ;
                    int rem = grow - b * LQQ;
                    int l = rem >> 10, yx = rem & 1023;
                    int h = gcol >> 5, d = gcol & 31;
                    g_vperm[((((b * NHH + h) * NLL + l) << 10) + yx) * HDD + d] =
                        __float2bfloat16(v);
                } else if (gcol < 1536) {
                    g_off[(size_t)grow * 1280 + (gcol - 256)] = v;
                } else {
                    g_aw[(size_t)grow * 640 + (gcol - 1536)] = v;
                }
            } else {
                v += bias[gcol];
                if (act) v = 0.5f * v * (1.0f + erff(v * 0.70710678118654752f));
                if (resid) v += resid[(size_t)grow * N + gcol];
                if (out_f32) out_f32[(size_t)grow * N + gcol] = v;
                if (out_bf16) out_bf16[(size_t)grow * N + gcol] = __float2bfloat16(v);
            }
        }
    }
}

// =====================================================================
// deformable sampling v4: two-phase + packed f32x2 accumulation
// =====================================================================
#define FFMA2(acc, v, w) \
    asm("fma.rn.f32x2 %0, %1, %2, %0;" : "+l"(acc) : "l"(v), "l"(w))

__global__ void sample_kernel(const float* __restrict__ refpts) {
    int warp = threadIdx.x >> 5, lane = threadIdx.x & 31;
    int unit = blockIdx.x * 8 + warp;                // 81920 units
    int token = unit >> 3;
    int h = unit & 7;
    int b = token / LQQ;

    __shared__ float s_aw[8][80];
    __shared__ float s_ref[8][10];
    __shared__ __align__(16) float s_wo[8][80 * 8];  // per sample: 4 x (wgt, byteoff)

    const float* awp = g_aw + (size_t)token * 640 + h * 80;
    for (int i = lane; i < 80; i += 32) s_aw[warp][i] = awp[i];
    const float* rp = refpts + (size_t)token * 10;
    if (lane < 10) s_ref[warp][lane] = rp[lane];
    __syncwarp();

    // ---- softmax over the 80 logits ----
    {
        float v0 = s_aw[warp][lane];
        float v1 = s_aw[warp][lane + 32];
        float v2 = (lane < 16) ? s_aw[warp][lane + 64] : -1e30f;
        float m = fmaxf(fmaxf(v0, v1), v2);
#pragma unroll
        for (int o = 16; o > 0; o >>= 1) m = fmaxf(m, __shfl_xor_sync(0xffffffffu, m, o));
        float e0 = expf(v0 - m), e1 = expf(v1 - m);
        float e2 = (lane < 16) ? expf(v2 - m) : 0.0f;
        float s = e0 + e1 + e2;
#pragma unroll
        for (int o = 16; o > 0; o >>= 1) s += __shfl_xor_sync(0xffffffffu, s, o);
        float inv = 1.0f / s;
        s_aw[warp][lane] = e0 * inv;
        s_aw[warp][lane + 32] = e1 * inv;
        if (lane < 16) s_aw[warp][lane + 64] = e2 * inv;
        __syncwarp();
    }

    // ---- phase 1: per-sample tap weights + BYTE offsets ----
    const float2* offp = (const float2*)(g_off + (size_t)token * 1280 + h * 160);
#pragma unroll
    for (int si = lane; si < 80; si += 32) {
        int l = si >> 4;
        float2 of = offp[si];
        float px = s_ref[warp][l * 2 + 0] * 32.0f - 0.5f + of.x;
        float py = s_ref[warp][l * 2 + 1] * 32.0f - 0.5f + of.y;
        float a  = s_aw[warp][si];
        float fx0 = floorf(px), fy0 = floorf(py);
        float fx = px - fx0, fy = py - fy0;
        int x0 = (int)fx0, y0 = (int)fy0;
        int lbase = l << 16;                       // level plane in BYTES
        float4 pk0, pk1;
        {   // tap 0
            bool ok = (x0 >= 0) && (x0 < 32) && (y0 >= 0) && (y0 < 32);
            int xc = min(max(x0, 0), 31), yc = min(max(y0, 0), 31);
            pk0.x = ok ? a * (1.0f - fx) * (1.0f - fy) : 0.0f;
            pk0.y = __int_as_float(lbase + (((yc << 5) + xc) << 6));
        }
        {   // tap 1
            int xi = x0 + 1;
            bool ok = (xi >= 0) && (xi < 32) && (y0 >= 0) && (y0 < 32);
            int xc = min(max(xi, 0), 31), yc = min(max(y0, 0), 31);
            pk0.z = ok ? a * fx * (1.0f - fy) : 0.0f;
            pk0.w = __int_as_float(lbase + (((yc << 5) + xc) << 6));
        }
        {   // tap 2
            int yi = y0 + 1;
            bool ok = (x0 >= 0) && (x0 < 32) && (yi >= 0) && (yi < 32);
            int xc = min(max(x0, 0), 31), yc = min(max(yi, 0), 31);
            pk1.x = ok ? a * (1.0f - fx) * fy : 0.0f;
            pk1.y = __int_as_float(lbase + (((yc << 5) + xc) << 6));
        }
        {   // tap 3
            int xi = x0 + 1, yi = y0 + 1;
            bool ok = (xi >= 0) && (xi < 32) && (yi >= 0) && (yi < 32);
            int xc = min(max(xi, 0), 31), yc = min(max(yi, 0), 31);
            pk1.z = ok ? a * fx * fy : 0.0f;
            pk1.w = __int_as_float(lbase + (((yc << 5) + xc) << 6));
        }
        *(float4*)&s_wo[warp][si * 8]     = pk0;
        *(float4*)&s_wo[warp][si * 8 + 4] = pk1;
    }
    __syncwarp();

    // ---- phase 2: load + packed f32x2 accumulate ----
    int q    = lane & 3;
    int tap  = (lane >> 2) & 3;
    int sgrp = lane >> 4;
    const float* wo = &s_wo[warp][tap * 2];
    const char* vbase = (const char*)
        (g_vperm + ((size_t)((b * NHH + h) * NLL) << 15) + (q << 3));

    uint64_t a0 = 0, a1 = 0, a2 = 0, a3 = 0;

#pragma unroll 8
    for (int r = 0; r < 40; ++r) {
        int s = r * 2 + sgrp;
        float2 p = *(const float2*)(wo + s * 8);
        uint32_t wb = __float_as_uint(p.x);
        uint64_t wpk;
        asm("mov.b64 %0, {%1, %2};" : "=l"(wpk) : "r"(wb), "r"(wb));
        uint4 u = *(const uint4*)(vbase + __float_as_int(p.y));
        uint64_t v;
        uint32_t lo, hi;
        lo = u.x << 16; hi = u.x & 0xFFFF0000u;
        asm("mov.b64 %0, {%1, %2};" : "=l"(v) : "r"(lo), "r"(hi));
        FFMA2(a0, v, wpk);
        lo = u.y << 16; hi = u.y & 0xFFFF0000u;
        asm("mov.b64 %0, {%1, %2};" : "=l"(v) : "r"(lo), "r"(hi));
        FFMA2(a1, v, wpk);
        lo = u.z << 16; hi = u.z & 0xFFFF0000u;
        asm("mov.b64 %0, {%1, %2};" : "=l"(v) : "r"(lo), "r"(hi));
        FFMA2(a2, v, wpk);
        lo = u.w << 16; hi = u.w & 0xFFFF0000u;
        asm("mov.b64 %0, {%1, %2};" : "=l"(v) : "r"(lo), "r"(hi));
        FFMA2(a3, v, wpk);
    }

    // unpack accumulators
    float2 acc0, acc1, acc2, acc3;
    {
        uint32_t lo, hi;
        asm("mov.b64 {%0, %1}, %2;" : "=r"(lo), "=r"(hi) : "l"(a0));
        acc0.x = __uint_as_float(lo); acc0.y = __uint_as_float(hi);
        asm("mov.b64 {%0, %1}, %2;" : "=r"(lo), "=r"(hi) : "l"(a1));
        acc1.x = __uint_as_float(lo); acc1.y = __uint_as_float(hi);
        asm("mov.b64 {%0, %1}, %2;" : "=r"(lo), "=r"(hi) : "l"(a2));
        acc2.x = __uint_as_float(lo); acc2.y = __uint_as_float(hi);
        asm("mov.b64 {%0, %1}, %2;" : "=r"(lo), "=r"(hi) : "l"(a3));
        acc3.x = __uint_as_float(lo); acc3.y = __uint_as_float(hi);
    }

    // reduce over tap (bits 2-3) and sgrp (bit 4)
#pragma unroll
    for (int o = 4; o <= 16; o <<= 1) {
        acc0.x += __shfl_xor_sync(0xffffffffu, acc0.x, o);
        acc0.y += __shfl_xor_sync(0xffffffffu, acc0.y, o);
        acc1.x += __shfl_xor_sync(0xffffffffu, acc1.x, o);
        acc1.y += __shfl_xor_sync(0xffffffffu, acc1.y, o);
        acc2.x += __shfl_xor_sync(0xffffffffu, acc2.x, o);
        acc2.y += __shfl_xor_sync(0xffffffffu, acc2.y, o);
        acc3.x += __shfl_xor_sync(0xffffffffu, acc3.x, o);
        acc3.y += __shfl_xor_sync(0xffffffffu, acc3.y, o);
    }

    if (lane < 4) {
        __nv_bfloat162 r0 = __floats2bfloat162_rn(acc0.x, acc0.y);
        __nv_bfloat162 r1 = __floats2bfloat162_rn(acc1.x, acc1.y);
        __nv_bfloat162 r2 = __floats2bfloat162_rn(acc2.x, acc2.y);
        __nv_bfloat162 r3 = __floats2bfloat162_rn(acc3.x, acc3.y);
        uint4 o;
        o.x = *(unsigned int*)&r0; o.y = *(unsigned int*)&r1;
        o.z = *(unsigned int*)&r2; o.w = *(unsigned int*)&r3;
        ((uint4*)(g_samp + (size_t)token * CC + h * 32))[q] = o;
    }
}

// =====================================================================
// launch
// =====================================================================
extern "C" void kernel_launch(void* const* d_in, const int* in_sizes, int n_in,
                              void* d_out, int out_size) {
    const float* x      = (const float*)d_in[0];
    const float* refpts = (const float*)d_in[1];
    const float* n3g = (const float*)d_in[4];
    const float* n3b = (const float*)d_in[5];
    const float* n4g = (const float*)d_in[6];
    const float* n4b = (const float*)d_in[7];
    const float* w_off  = (const float*)d_in[8];
    const float* b_off  = (const float*)d_in[9];
    const float* w_attn = (const float*)d_in[10];
    const float* b_attn = (const float*)d_in[11];
    const float* w_val  = (const float*)d_in[12];
    const float* b_val  = (const float*)d_in[13];
    const float* w_out  = (const float*)d_in[14];
    const float* b_out  = (const float*)d_in[15];
    const float* w_fc1  = (const float*)d_in[16];
    const float* b_fc1  = (const float*)d_in[17];
    const float* w_fc2  = (const float*)d_in[18];
    const float* b_fc2  = (const float*)d_in[19];
    float* outp = (float*)d_out;

    void *p_q, *p_hln, *p_samp, *p_mh, *p_x1;
    void *p_wp, *p_wou, *p_wf1, *p_wf2;
    cudaGetSymbolAddress(&p_q, g_q);
    cudaGetSymbolAddress(&p_hln, g_hln);
    cudaGetSymbolAddress(&p_samp, g_samp);
    cudaGetSymbolAddress(&p_mh, g_mh);
    cudaGetSymbolAddress(&p_x1, g_x1);
    cudaGetSymbolAddress(&p_wp, g_w_proj);
    cudaGetSymbolAddress(&p_wou, g_w_out);
    cudaGetSymbolAddress(&p_wf1, g_w_fc1);
    cudaGetSymbolAddress(&p_wf2, g_w_fc2);

    cudaFuncSetAttribute(gemm_bf16_kernel,
                         cudaFuncAttributeMaxDynamicSharedMemorySize, GSMEM);

    // 1. prep: LN1 + all weight packing (one launch, independent work)
    prep_kernel<<<PREP_BLOCKS, 256>>>(x, n3g, n3b,
                                      w_val, w_off, w_attn, b_val, b_off, b_attn,
                                      w_out, w_fc1, w_fc2);

    // 2. fused projection GEMM (val->vperm, off, attn) N=2176
    gemm_bf16_kernel<<<dim3(NPROJ / 128, MM / 128), 256, GSMEM>>>(
        (const __nv_bfloat16*)p_q, (const __nv_bfloat16*)p_wp, nullptr,
        nullptr, nullptr, nullptr, MM, NPROJ, CC, 0, 1);

    // 3. deformable sampling v4 (+fused softmax) -> g_samp
    sample_kernel<<<MM * NHH / 8, 256>>>(refpts);

    // 4. out-proj + residual(x) -> x1 (f32)
    gemm_bf16_kernel<<<dim3(CC / 128, MM / 128), 256, GSMEM>>>(
        (const __nv_bfloat16*)p_samp, (const __nv_bfloat16*)p_wou, b_out,
        x, (float*)p_x1, nullptr, MM, CC, CC, 0, 0);

    // 5. h = LN(x1) (bf16)
    ln_kernel<<<MM / 8, 256>>>((const float*)p_x1, n4g, n4b, (__nv_bfloat16*)p_hln);

    // 6. fc1 + GELU -> mh (bf16)
    gemm_bf16_kernel<<<dim3(MLPH / 128, MM / 128), 256, GSMEM>>>(
        (const __nv_bfloat16*)p_hln, (const __nv_bfloat16*)p_wf1, b_fc1,
        nullptr, nullptr, (__nv_bfloat16*)p_mh, MM, MLPH, CC, 1, 0);

    // 7. fc2 + residual(x1) -> d_out (f32)
    gemm_bf16_kernel<<<dim3(CC / 128, MM / 128), 256, GSMEM>>>(
        (const __nv_bfloat16*)p_mh, (const __nv_bfloat16*)p_wf2, b_fc2,
        (const float*)p_x1, outp, nullptr, MM, CC, MLPH, 0, 0);
}